// round 13
// baseline (speedup 1.0000x reference)
#include <cuda_runtime.h>
#include <cstdint>

#define NITEMS 4096
#define TPB    512
#define NWARP  16
#define CAP    600.0f
#define MU     1e-3f
#define MAXIT  16
#define LAM0   0.82f      // ensemble warm start (integral estimate lam* ~ 0.83)
#define PHITOL 5e-3f      // exit gate; first-order emit correction absorbs residual

__device__ __forceinline__ float frcp(float v) {
    float r;
    asm("rcp.approx.ftz.f32 %0, %1;" : "=f"(r) : "f"(v));
    return r;
}
__device__ __forceinline__ float frsq(float v) {
    float r;
    asm("rsqrt.approx.ftz.f32 %0, %1;" : "=f"(r) : "f"(v));
    return r;
}

__device__ __forceinline__ float wsum32(float v) {
#pragma unroll
    for (int o = 16; o > 0; o >>= 1) v += __shfl_xor_sync(0xffffffffu, v, o);
    return v;
}
// reduce 16 per-warp partials duplicated across the warp (idx = lane&15)
__device__ __forceinline__ float bsum16(float v) {
#pragma unroll
    for (int o = 8; o > 0; o >>= 1) v += __shfl_xor_sync(0xffffffffu, v, o);
    return v;
}

// interior root of g x^2 - (g+2mu) x + mu = 0, cancellation-free:
//   t(a) = 2mu/den, den = a + 2mu + sqrt(a^2+4mu^2), a=|g|; x = g>=0 ? t : 1-t
//   nd  = -dx/dg = (t/den)*(1 + a/D) = 1/H   (same value for both signs)

__global__ void __launch_bounds__(TPB, 2)
ipm_kernel(const float* __restrict__ costs,
           const float* __restrict__ wglob,
           float* __restrict__ out)
{
    __shared__ float4 sc[2 * TPB];          // costs row (raw; g = lam*w - cost)
    __shared__ float sR[2][3][NWARP];       // [parity][s1|s2|cv][warp]

    const int tid = threadIdx.x, lane = tid & 31, wid = tid >> 5;
    const float* crow = costs + (size_t)blockIdx.x * NITEMS;

    float wA[8], xA[8], ndA[8];             // plain float register arrays
    float lam = LAM0, lo = -30.0f, hi = 30.0f, dlam = 0.0f;
    float s1 = 0.0f, s2 = 0.0f, cvs = 0.0f;

    // ---- load + fused first evaluation at LAM0 (with curvature sum) --------
    {
        const float4* cg = (const float4*)crow;
        const float4* wg = (const float4*)wglob;
        const float4 cf0 = cg[tid], cf1 = cg[TPB + tid];
        const float4 w0 = wg[tid], w1 = wg[TPB + tid];
        sc[tid] = cf0; sc[TPB + tid] = cf1;   // fenced by first reduction barrier
        wA[0] = w0.x; wA[1] = w0.y; wA[2] = w0.z; wA[3] = w0.w;
        wA[4] = w1.x; wA[5] = w1.y; wA[6] = w1.z; wA[7] = w1.w;
        const float cA[8] = {cf0.x, cf0.y, cf0.z, cf0.w, cf1.x, cf1.y, cf1.z, cf1.w};
#pragma unroll
        for (int i = 0; i < 8; i++) {
            const float w    = wA[i];
            const float g    = fmaf(lam, w, -cA[i]);
            const float a    = fabsf(g);
            const float u    = fmaf(g, g, 4.0f * MU * MU);
            const float rD   = frsq(u);
            const float den  = fmaf(u, rD, a + 2.0f * MU);
            const float rden = frcp(den);
            const float t    = (2.0f * MU) * rden;
            const float e    = fmaf(a, rD, 1.0f);
            const float tr   = t * rden;
            const float nd   = tr * e;
            const float x    = (g >= 0.0f) ? t : 1.0f - t;
            xA[i] = x; ndA[i] = nd;
            const float w2 = w * w;
            s1 = fmaf(w, x, s1);
            s2 = fmaf(w2, nd, s2);
            // curvature: x'' = sign(g) * tr * (2 e^2 rden - 4mu^2/D^3)
            const float dpp   = (4.0f * MU * MU) * (rD * rD * rD);
            const float inner = fmaf(2.0f * e * e, rden, -dpp);
            const float tpp   = tr * inner;
            cvs = fmaf(w2 * w, (g >= 0.0f) ? tpp : -tpp, cvs);
        }
    }

    // ---- iteration 0: reduce 3 sums, guarded Halley step --------------------
    bool done = false;
    {
        float r1 = wsum32(s1), r2 = wsum32(s2), r3 = wsum32(cvs);
        if (lane == 0) { sR[0][0][wid] = r1; sR[0][1][wid] = r2; sR[0][2][wid] = r3; }
        __syncthreads();
        r1 = bsum16(sR[0][0][lane & 15]);
        r2 = bsum16(sR[0][1][lane & 15]);
        r3 = bsum16(sR[0][2][lane & 15]);
        const float phi = r1 - CAP;
        if (fabsf(phi) < PHITOL) {
            dlam = phi * frcp(r2);
            done = true;
        } else {
            if (phi > 0.0f) lo = lam; else hi = lam;   // phi monotone decreasing
            // Halley: step = phi*r2/(r2^2 - 0.5*phi*cv); accept only if the
            // denominator stays within [0.5, 2]x Newton's (step <= 2x Newton),
            // otherwise fall back to the plain Newton step (NEVER bisection).
            const float n2 = r2 * r2;
            const float dH = fmaf(-0.5f * phi, r3, n2);
            const float step = (dH > 0.5f * n2 && dH < 2.0f * n2)
                                   ? phi * r2 * frcp(dH)
                                   : phi * frcp(r2);
            float ln = lam + step;
            if (!(ln > lo && ln < hi)) ln = 0.5f * (lo + hi);
            lam = ln;
        }
    }

    // ---- iterations 1..: bracketed Newton, 2-sum reductions -----------------
    if (!done) {
#pragma unroll 1
        for (int it = 1; it < MAXIT; ++it) {
            s1 = 0.0f; s2 = 0.0f;
            const float4 cf0 = sc[tid], cf1 = sc[TPB + tid];
            const float cA[8] = {cf0.x, cf0.y, cf0.z, cf0.w, cf1.x, cf1.y, cf1.z, cf1.w};
#pragma unroll
            for (int i = 0; i < 8; i++) {
                const float w    = wA[i];
                const float g    = fmaf(lam, w, -cA[i]);
                const float a    = fabsf(g);
                const float u    = fmaf(g, g, 4.0f * MU * MU);
                const float rD   = frsq(u);
                const float den  = fmaf(u, rD, a + 2.0f * MU);
                const float rden = frcp(den);
                const float t    = (2.0f * MU) * rden;
                const float e    = fmaf(a, rD, 1.0f);
                const float nd   = (t * rden) * e;
                const float x    = (g >= 0.0f) ? t : 1.0f - t;
                xA[i] = x; ndA[i] = nd;
                s1 = fmaf(w, x, s1);
                s2 = fmaf(w * w, nd, s2);
            }
            float r1 = wsum32(s1), r2 = wsum32(s2);
            const int par = it & 1;
            if (lane == 0) { sR[par][0][wid] = r1; sR[par][1][wid] = r2; }
            __syncthreads();
            r1 = bsum16(sR[par][0][lane & 15]);
            r2 = bsum16(sR[par][1][lane & 15]);

            const float phi  = r1 - CAP;
            const float step = phi * frcp(r2);
            if (fabsf(phi) < PHITOL || it == MAXIT - 1) {
                dlam = step;                    // final first-order correction
                break;                          // xA/ndA match current lam
            }
            if (phi > 0.0f) lo = lam; else hi = lam;
            float ln = lam + step;
            if (!(ln > lo && ln < hi)) ln = 0.5f * (lo + hi);
            lam = ln;
        }
    }

    // ---- emit: out = x - dlam * w * nd  (== reference KKT refine) ----------
    {
        const float ndl = -dlam;
        float4* orow = (float4*)(out + (size_t)blockIdx.x * NITEMS);
        float4 o;
        o.x = fmaf(ndl * wA[0], ndA[0], xA[0]);
        o.y = fmaf(ndl * wA[1], ndA[1], xA[1]);
        o.z = fmaf(ndl * wA[2], ndA[2], xA[2]);
        o.w = fmaf(ndl * wA[3], ndA[3], xA[3]);
        orow[tid] = o;
        o.x = fmaf(ndl * wA[4], ndA[4], xA[4]);
        o.y = fmaf(ndl * wA[5], ndA[5], xA[5]);
        o.z = fmaf(ndl * wA[6], ndA[6], xA[6]);
        o.w = fmaf(ndl * wA[7], ndA[7], xA[7]);
        orow[TPB + tid] = o;
    }
}

extern "C" void kernel_launch(void* const* d_in, const int* in_sizes, int n_in,
                              void* d_out, int out_size)
{
    const float* costs = (const float*)d_in[0];
    const float* wv    = (const float*)d_in[1];
    int costs_elems = in_sizes[0];
    if (n_in >= 2 && in_sizes[0] == NITEMS && in_sizes[1] > NITEMS) {
        costs = (const float*)d_in[1];
        wv    = (const float*)d_in[0];
        costs_elems = in_sizes[1];
    }
    const int B = costs_elems / NITEMS;
    ipm_kernel<<<B, TPB>>>(costs, wv, (float*)d_out);
}

// round 14
// speedup vs baseline: 1.6992x; 1.6992x over previous
#include <cuda_runtime.h>
#include <cstdint>

#define NITEMS 4096
#define TPB    512
#define NWARP  16
#define CAP    600.0f
#define MU     1e-3f
#define MAXIT  16
#define LAM0   0.82f       // ensemble warm start (integral estimate lam* ~ 0.83)
#define PHI_EMIT 0.15f     // exit gate; 2nd-order emit absorbs dlam up to ~3e-4

typedef unsigned long long u64p;   // packed f32x2

__device__ __forceinline__ float frcp(float v) {
    float r;
    asm("rcp.approx.ftz.f32 %0, %1;" : "=f"(r) : "f"(v));
    return r;
}
__device__ __forceinline__ float frsq(float v) {
    float r;
    asm("rsqrt.approx.ftz.f32 %0, %1;" : "=f"(r) : "f"(v));
    return r;
}
__device__ __forceinline__ u64p pack2(float lo, float hi) {
    u64p r;
    asm("mov.b64 %0, {%1, %2};" : "=l"(r) : "f"(lo), "f"(hi));
    return r;
}
__device__ __forceinline__ void unpack2(u64p v, float& lo, float& hi) {
    asm("mov.b64 {%0, %1}, %2;" : "=f"(lo), "=f"(hi) : "l"(v));
}

__device__ __forceinline__ float wsum32(float v) {
#pragma unroll
    for (int o = 16; o > 0; o >>= 1) v += __shfl_xor_sync(0xffffffffu, v, o);
    return v;
}
// reduce 16 per-warp partials duplicated across the warp (idx = lane&15)
__device__ __forceinline__ float bsum16(float v) {
#pragma unroll
    for (int o = 8; o > 0; o >>= 1) v += __shfl_xor_sync(0xffffffffu, v, o);
    return v;
}

// interior root of g x^2 - (g+2mu) x + mu = 0, cancellation-free:
//   t(a) = 2mu / (a + 2mu + sqrt(a^2+4mu^2)),  a = |g|;  x = g>=0 ? t : 1-t
// nd = -dx/dg = t * rden * (1 + a/D) = 1/H  (same value for both signs)
__device__ __forceinline__ void xofg(float g, float& x, float& nd) {
    const float a    = fabsf(g);
    const float u    = fmaf(a, a, 4.0f * MU * MU);
    const float rD   = frsq(u);
    const float den  = fmaf(u, rD, a + 2.0f * MU);   // a + 2mu + sqrt(u)
    const float rden = frcp(den);
    const float t    = (2.0f * MU) * rden;
    x  = (g >= 0.0f) ? t : 1.0f - t;
    nd = (t * rden) * fmaf(a, rD, 1.0f);
}

// one elementwise evaluation quad at lam, accumulating s1/s2 and stashing x, nd
#define EVAL_QUAD(cf, wf, base)                                              \
    do {                                                                     \
        float x0, x1, x2, x3, n0, n1, n2, n3;                                \
        xofg(fmaf(lam, wf.x, -cf.x), x0, n0);                                \
        s1 = fmaf(wf.x, x0, s1); s2 = fmaf(wf.x * wf.x, n0, s2);             \
        xofg(fmaf(lam, wf.y, -cf.y), x1, n1);                                \
        s1 = fmaf(wf.y, x1, s1); s2 = fmaf(wf.y * wf.y, n1, s2);             \
        xofg(fmaf(lam, wf.z, -cf.z), x2, n2);                                \
        s1 = fmaf(wf.z, x2, s1); s2 = fmaf(wf.z * wf.z, n2, s2);             \
        xofg(fmaf(lam, wf.w, -cf.w), x3, n3);                                \
        s1 = fmaf(wf.w, x3, s1); s2 = fmaf(wf.w * wf.w, n3, s2);             \
        xP[base]      = pack2(x0, x1);                                       \
        xP[base + 1]  = pack2(x2, x3);                                       \
        ndP[base]     = pack2(n0, n1);                                       \
        ndP[base + 1] = pack2(n2, n3);                                       \
    } while (0)

// second-order emit for one element:
//   out = x + x'*(w*dlam) + 0.5*x''*(w*dlam)^2,  x' = -nd,
//   x'' = 2*nd*(t1 - g*nd)/Fx,  t1 = 2x-1,  Fx = g*t1 - 2mu  (|Fx| >= 2mu)
__device__ __forceinline__ float emit_one(float x, float nd, float w,
                                          float c, float lam, float dlam) {
    const float g   = fmaf(lam, w, -c);
    const float wd  = w * dlam;
    const float t1  = fmaf(2.0f, x, -1.0f);
    const float Fx  = fmaf(g, t1, -2.0f * MU);
    const float num = 2.0f * nd * fmaf(-g, nd, t1);
    const float xpp = num * frcp(Fx);
    const float o1  = fmaf(-wd, nd, x);                 // first order
    return fmaf(0.5f * wd * wd, xpp, o1);               // + second order
}

__global__ void __launch_bounds__(TPB, 2)
ipm_kernel(const float* __restrict__ costs,
           const float* __restrict__ wglob,
           float* __restrict__ out)
{
    __shared__ float4 sc[2 * TPB];          // costs row (raw; g = lam*w - cost)
    __shared__ float sR[2][2][NWARP];       // [parity][s1|s2][warp]

    const int tid = threadIdx.x, lane = tid & 31, wid = tid >> 5;
    const float* crow = costs + (size_t)blockIdx.x * NITEMS;

    float lam = LAM0, lo = -30.0f, hi = 30.0f;
    u64p xP[4], ndP[4];
    float dlam = 0.0f;
    float4 wf0, wf1;                        // weights resident in registers
    float s1 = 0.0f, s2 = 0.0f;

    // ---- load + fused first evaluation at LAM0 -----------------------------
    {
        const float4* cg = (const float4*)crow;
        const float4* wg = (const float4*)wglob;
        const float4 cf0 = cg[tid], cf1 = cg[TPB + tid];
        wf0 = wg[tid]; wf1 = wg[TPB + tid];
        sc[tid] = cf0; sc[TPB + tid] = cf1;
        EVAL_QUAD(cf0, wf0, 0);
        EVAL_QUAD(cf1, wf1, 2);
        // sc stores are fenced by the __syncthreads in the first reduction
    }

    // ---- 1-D safeguarded (bracketed) Newton on lambda ----------------------
    //   phi(lam) = sum w*x(lam) - CAP,  phi' = -s2
    // Exit when |phi| < PHI_EMIT; the pending Newton increment dlam = phi/s2
    // is applied per-element at emit with a 2nd-order Taylor correction.
#pragma unroll 1
    for (int it = 0; it < MAXIT; ++it) {
        float r1 = wsum32(s1), r2 = wsum32(s2);
        const int par = it & 1;
        if (lane == 0) { sR[par][0][wid] = r1; sR[par][1][wid] = r2; }
        __syncthreads();
        r1 = bsum16(sR[par][0][lane & 15]);     // identical in all threads
        r2 = bsum16(sR[par][1][lane & 15]);

        const float phi  = r1 - CAP;
        const float step = phi * frcp(r2);      // Newton increment
        if (fabsf(phi) < PHI_EMIT || it == MAXIT - 1) {
            dlam = step;                        // applied at emit (2nd order)
            break;                              // xP/ndP match current lam
        }
        if (phi > 0.0f) lo = lam; else hi = lam;   // phi monotone decreasing
        float ln = lam + step;
        if (!(ln > lo && ln < hi)) ln = 0.5f * (lo + hi);
        lam = ln;

        // next evaluation: costs from shared, weights from registers
        s1 = 0.0f; s2 = 0.0f;
        {
            const float4 cf0 = sc[tid], cf1 = sc[TPB + tid];
            EVAL_QUAD(cf0, wf0, 0);
            EVAL_QUAD(cf1, wf1, 2);
        }
    }

    // ---- emit: out = x - dlam*w*nd + 0.5*(dlam*w)^2*x''  -------------------
    {
        const float4 cf0 = sc[tid], cf1 = sc[TPB + tid];
        float4* orow = (float4*)(out + (size_t)blockIdx.x * NITEMS);
        float x0, x1, x2, x3, n0, n1, n2, n3;
        float4 o;
        unpack2(xP[0], x0, x1);  unpack2(xP[1], x2, x3);
        unpack2(ndP[0], n0, n1); unpack2(ndP[1], n2, n3);
        o.x = emit_one(x0, n0, wf0.x, cf0.x, lam, dlam);
        o.y = emit_one(x1, n1, wf0.y, cf0.y, lam, dlam);
        o.z = emit_one(x2, n2, wf0.z, cf0.z, lam, dlam);
        o.w = emit_one(x3, n3, wf0.w, cf0.w, lam, dlam);
        orow[tid] = o;
        unpack2(xP[2], x0, x1);  unpack2(xP[3], x2, x3);
        unpack2(ndP[2], n0, n1); unpack2(ndP[3], n2, n3);
        o.x = emit_one(x0, n0, wf1.x, cf1.x, lam, dlam);
        o.y = emit_one(x1, n1, wf1.y, cf1.y, lam, dlam);
        o.z = emit_one(x2, n2, wf1.z, cf1.z, lam, dlam);
        o.w = emit_one(x3, n3, wf1.w, cf1.w, lam, dlam);
        orow[TPB + tid] = o;
    }
}

extern "C" void kernel_launch(void* const* d_in, const int* in_sizes, int n_in,
                              void* d_out, int out_size)
{
    const float* costs = (const float*)d_in[0];
    const float* wv    = (const float*)d_in[1];
    int costs_elems = in_sizes[0];
    if (n_in >= 2 && in_sizes[0] == NITEMS && in_sizes[1] > NITEMS) {
        costs = (const float*)d_in[1];
        wv    = (const float*)d_in[0];
        costs_elems = in_sizes[1];
    }
    const int B = costs_elems / NITEMS;
    ipm_kernel<<<B, TPB>>>(costs, wv, (float*)d_out);
}